// round 8
// baseline (speedup 1.0000x reference)
#include <cuda_runtime.h>
#include <cstdint>
#include <cstddef>

#define TL 512
#define NB 2048
#define NB16 (NB*16)
#define FULL 0xffffffffu

// scratch: hproj_seq and z_seq, each T*B*16 floats = 64 MiB
__device__ float g_hproj[(size_t)TL * NB * 16];
__device__ float g_zseq[(size_t)TL * NB * 16];

// hardware tanh (sm_75+; 1 MUFU op)
__device__ __forceinline__ float htanh(float x){
  float y; asm("tanh.approx.f32 %0, %1;" : "=f"(y) : "f"(x)); return y;
}
__device__ __forceinline__ float hsig(float x){
  return fmaf(0.5f, htanh(0.5f * x), 0.5f);
}

// ---- packed f32x2 helpers ----
__device__ __forceinline__ uint64_t pk2(float lo, float hi){
  uint64_t r; asm("mov.b64 %0, {%1, %2};" : "=l"(r) : "f"(lo), "f"(hi)); return r;
}
__device__ __forceinline__ uint64_t fma2(uint64_t a, uint64_t b, uint64_t c){
  uint64_t d; asm("fma.rn.f32x2 %0, %1, %2, %3;" : "=l"(d) : "l"(a), "l"(b), "l"(c));
  return d;
}
__device__ __forceinline__ float dot16p(const uint64_t w[8], const uint64_t v[8]){
  const uint64_t z = 0;
  uint64_t a0 = fma2(w[0], v[0], z);
  uint64_t a1 = fma2(w[1], v[1], z);
  a0 = fma2(w[2], v[2], a0);
  a1 = fma2(w[3], v[3], a1);
  a0 = fma2(w[4], v[4], a0);
  a1 = fma2(w[5], v[5], a1);
  a0 = fma2(w[6], v[6], a0);
  a1 = fma2(w[7], v[7], a1);
  uint64_t s; asm("add.rn.f32x2 %0, %1, %2;" : "=l"(s) : "l"(a0), "l"(a1));
  float lo, hi; asm("mov.b64 {%0, %1}, %2;" : "=f"(lo), "=f"(hi) : "l"(s));
  return lo + hi;
}
__device__ __forceinline__ void ldv8p(const float* p, uint64_t v[8]){
  #pragma unroll
  for (int i = 0; i < 4; i++){
    ulonglong2 q = reinterpret_cast<const ulonglong2*>(p)[i];
    v[2*i] = q.x; v[2*i+1] = q.y;
  }
}
__device__ __forceinline__ void ldv16(const float* p, float v[16]){
  #pragma unroll
  for (int i = 0; i < 4; i++){
    float4 q = reinterpret_cast<const float4*>(p)[i];
    v[4*i+0] = q.x; v[4*i+1] = q.y; v[4*i+2] = q.z; v[4*i+3] = q.w;
  }
}

// broadcast 16 low-lane scalars to all lanes
#define BCAST16(dst, src)                                  \
  {                                                        \
    _Pragma("unroll")                                      \
    for (int j = 0; j < 16; j++)                           \
      dst[j] = __shfl_sync(FULL, (src), j);                \
  }

// ============================================================================
// Phase 1: backward LSTM scan + fused hproj. One warp per batch element.
// Register-resident h/c (dup in both halves), shfl broadcast, no smem.
// Lane l<16: rows lo (i) and lo+32 (g). Lane l>=16: rows lo+16 (f), lo+48 (o).
// ============================================================================
__global__ __launch_bounds__(64)
void lstm_bwd_kernel(const float* __restrict__ x,
                     const float* __restrict__ Wih,
                     const float* __restrict__ Whh,
                     const float* __restrict__ bih,
                     const float* __restrict__ bhh,
                     const float* __restrict__ cW1,
                     const float* __restrict__ cb1)
{
  const int l = threadIdx.x & 31;
  const int w = threadIdx.x >> 5;
  const int b = blockIdx.x * 2 + w;
  const int lo = l & 15;
  const bool low = (l < 16);

  const int r0 = l, r1 = l + 32;
  uint64_t w0[8], w1[8], wHp[8];
  #pragma unroll
  for (int j = 0; j < 8; j++){
    w0[j]  = pk2(Whh[r0*16 + 2*j], Whh[r0*16 + 2*j + 1]);
    w1[j]  = pk2(Whh[r1*16 + 2*j], Whh[r1*16 + 2*j + 1]);
    wHp[j] = pk2(cW1[lo*32 + 2*j], cW1[lo*32 + 2*j + 1]);
  }
  const float wx0 = Wih[r0], wx1 = Wih[r1];
  const float b0 = bih[r0] + bhh[r0];
  const float b1 = bih[r1] + bhh[r1];
  const float bHp = cb1[lo];

  // act2 = low ? tanh(a1) : sig(a1) = m*htanh(k*a1)+d
  const float k2 = low ? 1.f : 0.5f;
  const float m2 = low ? 1.f : 0.5f;
  const float d2 = low ? 0.f : 0.5f;

  float hcur = 0.f, c = 0.f;

  const float* xb = x + b;
  float* hpout = g_hproj + (size_t)b * 16 + lo;

  float xt = __ldg(xb + (size_t)(TL-1) * NB);

  for (int t = TL - 1; t >= 0; --t){
    float xn = 0.f;
    if (t > 0) xn = __ldg(xb + (size_t)(t-1) * NB);   // off-chain prefetch

    float hb[16]; BCAST16(hb, hcur);
    uint64_t hv[8];
    #pragma unroll
    for (int j = 0; j < 8; j++) hv[j] = pk2(hb[2*j], hb[2*j+1]);

    // hproj of h[t+1] (current state); skip first iteration
    float hp = bHp + dot16p(wHp, hv);
    if (low && t != TL - 1)
      hpout[(size_t)(t+1) * NB16] = hp;

    float a0 = fmaf(xt, wx0, b0) + dot16p(w0, hv);
    float a1 = fmaf(xt, wx1, b1) + dot16p(w1, hv);

    float act1 = hsig(a0);                          // sig(i) / sig(f)
    float act2 = fmaf(m2, htanh(k2 * a1), d2);      // tanh(g) / sig(o)
    float p = low ? act1 * act2 : act1;             // low: sig(i)*tanh(g); high: sig(f)
    float q = act2;                                 // high: sig(o)

    float pp = __shfl_xor_sync(FULL, p, 16);
    float qq = __shfl_xor_sync(FULL, q, 16);
    float ig = low ? p  : pp;
    float ff = low ? pp : p;
    float oo = low ? qq : q;

    c = fmaf(ff, c, ig);
    hcur = oo * htanh(c);
    xt = xn;
  }

  // epilogue: hproj[0] from final h
  {
    float hb[16]; BCAST16(hb, hcur);
    uint64_t hv[8];
    #pragma unroll
    for (int j = 0; j < 8; j++) hv[j] = pk2(hb[2*j], hb[2*j+1]);
    float hp = bHp + dot16p(wHp, hv);
    if (low) hpout[0] = hp;
  }
}

// ============================================================================
// Phase 2: DKF recurrence. One warp per batch, smem staging (R5 transport),
// 4-deep prefetch ring, packed FFMA2 dots, hardware tanh.
// ============================================================================
__global__ __launch_bounds__(64)
void dkf_rec_kernel(const float* __restrict__ eps,
                    const float* __restrict__ cW1,
                    const float* __restrict__ cW2, const float* __restrict__ cb2,
                    const float* __restrict__ eW1, const float* __restrict__ eb1,
                    const float* __restrict__ eW2, const float* __restrict__ eb2,
                    float* __restrict__ out)
{
  const int l = threadIdx.x & 31;
  const int w = threadIdx.x >> 5;
  const int b = blockIdx.x * 2 + w;
  const int lo = l & 15;

  __shared__ __align__(16) float sm[2][48];
  float* SA = &sm[w][0];    // a1 (16)
  float* SC = &sm[w][16];   // e1 (16)
  float* SZ = &sm[w][32];   // z  (16)

  // layer A, z-columns of comb_W1, row lo (duplicated across halves)
  uint64_t wAz[8];
  #pragma unroll
  for (int j = 0; j < 8; j++)
    wAz[j] = pk2(cW1[lo*32 + 16 + 2*j], cW1[lo*32 + 16 + 2*j + 1]);

  // fused M row lo: M = eW1 @ cW2 ; bM = eW1 @ cb2 + eb1
  uint64_t wM[8];
  float bM = eb1[lo];
  {
    float e1w[8];
    #pragma unroll
    for (int k = 0; k < 8; k++) e1w[k] = eW1[lo*8 + k];
    #pragma unroll
    for (int cc = 0; cc < 8; cc++){
      float accx = 0.f, accy = 0.f;
      #pragma unroll
      for (int k = 0; k < 8; k++){
        accx = fmaf(e1w[k], cW2[k*16 + 2*cc],     accx);
        accy = fmaf(e1w[k], cW2[k*16 + 2*cc + 1], accy);
      }
      wM[cc] = pk2(accx, accy);
    }
    #pragma unroll
    for (int k = 0; k < 8; k++) bM = fmaf(e1w[k], cb2[k], bM);
  }

  // enc2 (32x16): lane l owns row l
  uint64_t wD[8];
  #pragma unroll
  for (int j = 0; j < 8; j++)
    wD[j] = pk2(eW2[l*16 + 2*j], eW2[l*16 + 2*j + 1]);
  const float bD = eb2[l];

  if (l < 16) SZ[lo] = 0.f;      // z0
  __syncwarp();

  const float* hpp = g_hproj + (size_t)b * 16 + lo;
  const float* epp = eps     + (size_t)b * 16 + lo;
  float*       zsp = g_zseq  + (size_t)b * 16 + lo;
  float*       outp = out    + (size_t)b * 66;

  // ---- 4-deep prefetch ring ----
  float hp0 = __ldg(hpp);
  float hp1 = __ldg(hpp + (size_t)1 * NB16);
  float hp2 = __ldg(hpp + (size_t)2 * NB16);
  float hp3 = __ldg(hpp + (size_t)3 * NB16);
  float ep0 = __ldg(epp);
  float ep1 = __ldg(epp + (size_t)1 * NB16);
  float ep2 = __ldg(epp + (size_t)2 * NB16);
  float ep3 = __ldg(epp + (size_t)3 * NB16);

  #define DKF_STEP(T, HPV, EPSV)                                          \
  {                                                                       \
    uint64_t zv[8]; ldv8p(SZ, zv);                                        \
    float a1 = htanh((HPV) + dot16p(wAz, zv));                            \
    if (l < 16) SA[lo] = a1;                                              \
    __syncwarp();                                                         \
    uint64_t av[8]; ldv8p(SA, av);                                        \
    float e1 = htanh(bM + dot16p(wM, av));                                \
    if (l < 16) SC[lo] = e1;                                              \
    __syncwarp();                                                         \
    uint64_t ev[8]; ldv8p(SC, ev);                                        \
    float e2 = bD + dot16p(wD, ev);                                       \
    outp[2 + l] = e2;                                                     \
    float lvz = __shfl_xor_sync(FULL, e2, 16);                            \
    float znew = fmaf((EPSV), __expf(0.5f * lvz), e2);                    \
    if (l < 16){                                                          \
      SZ[lo] = znew;                                                      \
      zsp[(size_t)(T) * NB16] = znew;                                     \
    }                                                                     \
    __syncwarp();                                                         \
    outp += (size_t)NB * 66;                                              \
  }

  #pragma unroll 1
  for (int t = 0; t < TL; t += 4){
    int t4 = t + 4; if (t4 > TL-1) t4 = TL-1;
    int t5 = t + 5; if (t5 > TL-1) t5 = TL-1;
    int t6 = t + 6; if (t6 > TL-1) t6 = TL-1;
    int t7 = t + 7; if (t7 > TL-1) t7 = TL-1;

    float hpa = __ldg(hpp + (size_t)t4 * NB16);
    float epa = __ldg(epp + (size_t)t4 * NB16);
    DKF_STEP(t + 0, hp0, ep0);
    hp0 = hpa; ep0 = epa;

    float hpb = __ldg(hpp + (size_t)t5 * NB16);
    float epb = __ldg(epp + (size_t)t5 * NB16);
    DKF_STEP(t + 1, hp1, ep1);
    hp1 = hpb; ep1 = epb;

    float hpc = __ldg(hpp + (size_t)t6 * NB16);
    float epc = __ldg(epp + (size_t)t6 * NB16);
    DKF_STEP(t + 2, hp2, ep2);
    hp2 = hpc; ep2 = epc;

    float hpd = __ldg(hpp + (size_t)t7 * NB16);
    float epd = __ldg(epp + (size_t)t7 * NB16);
    DKF_STEP(t + 3, hp3, ep3);
    hp3 = hpd; ep3 = epd;
  }
  #undef DKF_STEP
}

// ============================================================================
// Phase 3: decoder + transition. Fully parallel over all (t,b) positions.
// ============================================================================
#define OD_W1 0
#define OD_B1 256
#define OD_W2 272
#define OD_B2 304
#define OT_W1 308
#define OT_B1 564
#define OT_W2 580
#define OT_B2 1092
#define SW_TOT 1124

__device__ __forceinline__ float sdot16(const float* srow, const float v[16]){
  float a0 = 0.f, a1 = 0.f, a2 = 0.f, a3 = 0.f;
  #pragma unroll
  for (int j = 0; j < 4; j++){
    float4 q = reinterpret_cast<const float4*>(srow)[j];
    a0 = fmaf(q.x, v[4*j+0], a0);
    a1 = fmaf(q.y, v[4*j+1], a1);
    a2 = fmaf(q.z, v[4*j+2], a2);
    a3 = fmaf(q.w, v[4*j+3], a3);
  }
  return (a0 + a1) + (a2 + a3);
}

__global__ __launch_bounds__(256)
void dectr_kernel(const float* __restrict__ dW1, const float* __restrict__ db1,
                  const float* __restrict__ dW2, const float* __restrict__ db2,
                  const float* __restrict__ tW1, const float* __restrict__ tb1,
                  const float* __restrict__ tW2, const float* __restrict__ tb2,
                  float* __restrict__ out)
{
  __shared__ __align__(16) float s[SW_TOT];
  const int tid = threadIdx.x;
  for (int i = tid; i < 256; i += 256) s[OD_W1 + i] = dW1[i];
  if (tid < 16)  s[OD_B1 + tid] = db1[tid];
  if (tid < 32)  s[OD_W2 + tid] = dW2[tid];
  if (tid < 2)   s[OD_B2 + tid] = db2[tid];
  for (int i = tid; i < 256; i += 256) s[OT_W1 + i] = tW1[i];
  if (tid < 16)  s[OT_B1 + tid] = tb1[tid];
  for (int i = tid; i < 512; i += 256) s[OT_W2 + i] = tW2[i];
  if (tid < 32)  s[OT_B2 + tid] = tb2[tid];
  __syncthreads();

  const size_t pos = (size_t)blockIdx.x * 256 + tid;   // t*NB + b
  const float* zp_ptr = g_zseq + pos * 16;

  float z[16]; ldv16(zp_ptr, z);
  float zp[16];
  if (pos >= NB){ ldv16(zp_ptr - (size_t)NB * 16, zp); }
  else {
    #pragma unroll
    for (int j = 0; j < 16; j++) zp[j] = 0.f;
  }

  float* ob = out + pos * 66;

  float d1[16];
  #pragma unroll
  for (int r = 0; r < 16; r++)
    d1[r] = htanh(s[OD_B1 + r] + sdot16(&s[OD_W1 + r*16], z));
  float2 dx;
  dx.x = s[OD_B2 + 0] + sdot16(&s[OD_W2 + 0],  d1);
  dx.y = s[OD_B2 + 1] + sdot16(&s[OD_W2 + 16], d1);
  *reinterpret_cast<float2*>(ob) = dx;    // mu_x, logvar_x

  float t1[16];
  #pragma unroll
  for (int r = 0; r < 16; r++)
    t1[r] = htanh(s[OT_B1 + r] + sdot16(&s[OT_W1 + r*16], zp));
  #pragma unroll
  for (int r = 0; r < 32; r += 2){
    float2 tv;
    tv.x = s[OT_B2 + r]     + sdot16(&s[OT_W2 + r*16],     t1);
    tv.y = s[OT_B2 + r + 1] + sdot16(&s[OT_W2 + (r+1)*16], t1);
    *reinterpret_cast<float2*>(ob + 34 + r) = tv;   // mu_tr / logvar_tr
  }
}

extern "C" void kernel_launch(void* const* d_in, const int* in_sizes, int n_in,
                              void* d_out, int out_size)
{
  const float* x   = (const float*)d_in[0];
  const float* eps = (const float*)d_in[1];
  const float* Wih = (const float*)d_in[2];
  const float* Whh = (const float*)d_in[3];
  const float* bih = (const float*)d_in[4];
  const float* bhh = (const float*)d_in[5];
  const float* cW1 = (const float*)d_in[6];
  const float* cb1 = (const float*)d_in[7];
  const float* cW2 = (const float*)d_in[8];
  const float* cb2 = (const float*)d_in[9];
  const float* eW1 = (const float*)d_in[10];
  const float* eb1 = (const float*)d_in[11];
  const float* eW2 = (const float*)d_in[12];
  const float* eb2 = (const float*)d_in[13];
  const float* dW1 = (const float*)d_in[14];
  const float* db1 = (const float*)d_in[15];
  const float* dW2 = (const float*)d_in[16];
  const float* db2 = (const float*)d_in[17];
  const float* tW1 = (const float*)d_in[18];
  const float* tb1 = (const float*)d_in[19];
  const float* tW2 = (const float*)d_in[20];
  const float* tb2 = (const float*)d_in[21];
  float* out = (float*)d_out;

  lstm_bwd_kernel<<<NB/2, 64>>>(x, Wih, Whh, bih, bhh, cW1, cb1);
  dkf_rec_kernel<<<NB/2, 64>>>(eps, cW1, cW2, cb2, eW1, eb1, eW2, eb2, out);
  dectr_kernel<<<(TL*NB)/256, 256>>>(dW1, db1, dW2, db2, tW1, tb1, tW2, tb2, out);
}

// round 9
// speedup vs baseline: 1.3159x; 1.3159x over previous
#include <cuda_runtime.h>
#include <cstdint>
#include <cstddef>

#define TL 512
#define NB 2048
#define NB16 (NB*16)
#define FULL 0xffffffffu

// scratch: hproj_seq and z_seq, each T*B*16 floats = 64 MiB
__device__ float g_hproj[(size_t)TL * NB * 16];
__device__ float g_zseq[(size_t)TL * NB * 16];

__device__ __forceinline__ float sigf(float x){
  return __fdividef(1.f, 1.f + __expf(-x));
}
__device__ __forceinline__ float tanh_fast(float x){
  return __fdividef(2.f, 1.f + __expf(-2.f * x)) - 1.f;
}

// ---- packed f32x2 helpers ----
__device__ __forceinline__ uint64_t pk2(float lo, float hi){
  uint64_t r; asm("mov.b64 %0, {%1, %2};" : "=l"(r) : "f"(lo), "f"(hi)); return r;
}
__device__ __forceinline__ uint64_t fma2(uint64_t a, uint64_t b, uint64_t c){
  uint64_t d; asm("fma.rn.f32x2 %0, %1, %2, %3;" : "=l"(d) : "l"(a), "l"(b), "l"(c));
  return d;
}
__device__ __forceinline__ float dot16p(const uint64_t w[8], const uint64_t v[8]){
  const uint64_t z = 0;
  uint64_t a0 = fma2(w[0], v[0], z);
  uint64_t a1 = fma2(w[1], v[1], z);
  a0 = fma2(w[2], v[2], a0);
  a1 = fma2(w[3], v[3], a1);
  a0 = fma2(w[4], v[4], a0);
  a1 = fma2(w[5], v[5], a1);
  a0 = fma2(w[6], v[6], a0);
  a1 = fma2(w[7], v[7], a1);
  uint64_t s; asm("add.rn.f32x2 %0, %1, %2;" : "=l"(s) : "l"(a0), "l"(a1));
  float lo, hi; asm("mov.b64 {%0, %1}, %2;" : "=f"(lo), "=f"(hi) : "l"(s));
  return lo + hi;
}
__device__ __forceinline__ void ldv8p(const float* p, uint64_t v[8]){
  #pragma unroll
  for (int i = 0; i < 4; i++){
    ulonglong2 q = reinterpret_cast<const ulonglong2*>(p)[i];
    v[2*i] = q.x; v[2*i+1] = q.y;
  }
}
__device__ __forceinline__ void ldv16(const float* p, float v[16]){
  #pragma unroll
  for (int i = 0; i < 4; i++){
    float4 q = reinterpret_cast<const float4*>(p)[i];
    v[4*i+0] = q.x; v[4*i+1] = q.y; v[4*i+2] = q.z; v[4*i+3] = q.w;
  }
}

// ============================================================================
// Phase 1: backward LSTM scan + fused hproj. TWO batches per warp (independent
// chains, shared weights). Lanes 0-15: rows l (i), l+32 (g); lanes 16-31:
// rows l (f), l+32 (o) — per batch. smem staging for h.
// ============================================================================
__global__ __launch_bounds__(64)
void lstm_bwd_kernel(const float* __restrict__ x,
                     const float* __restrict__ Wih,
                     const float* __restrict__ Whh,
                     const float* __restrict__ bih,
                     const float* __restrict__ bhh,
                     const float* __restrict__ cW1,
                     const float* __restrict__ cb1)
{
  const int l = threadIdx.x & 31;
  const int w = threadIdx.x >> 5;
  const int bA = blockIdx.x * 4 + w * 2;   // batches bA, bA+1
  const int lo = l & 15;
  const bool low = (l < 16);

  __shared__ __align__(16) float sH[2][2][16];
  float* hbufA = sH[w][0];
  float* hbufB = sH[w][1];

  const int r0 = l, r1 = l + 32;
  uint64_t w0[8], w1[8], wHp[8];
  #pragma unroll
  for (int j = 0; j < 8; j++){
    w0[j]  = pk2(Whh[r0*16 + 2*j], Whh[r0*16 + 2*j + 1]);
    w1[j]  = pk2(Whh[r1*16 + 2*j], Whh[r1*16 + 2*j + 1]);
    wHp[j] = pk2(cW1[lo*32 + 2*j], cW1[lo*32 + 2*j + 1]);
  }
  const float wx0 = Wih[r0], wx1 = Wih[r1];
  const float b0 = bih[r0] + bhh[r0];
  const float b1 = bih[r1] + bhh[r1];
  const float bHp = cb1[lo];
  const float sc2 = low ? 2.f : 1.f;   // act2 = tanh (low) / sigmoid (high)

  if (low){ hbufA[lo] = 0.f; hbufB[lo] = 0.f; }
  float cA = 0.f, cB = 0.f;
  __syncwarp();

  const float* xb = x + bA;                                // B at +1
  float* hpout = g_hproj + (size_t)bA * 16 + lo;           // B at +16

  float xtA = __ldg(xb + (size_t)(TL-1) * NB);
  float xtB = __ldg(xb + (size_t)(TL-1) * NB + 1);

  for (int t = TL - 1; t >= 0; --t){
    float xnA = 0.f, xnB = 0.f;
    if (t > 0){
      xnA = __ldg(xb + (size_t)(t-1) * NB);
      xnB = __ldg(xb + (size_t)(t-1) * NB + 1);
    }

    uint64_t hvA[8]; ldv8p(hbufA, hvA);
    uint64_t hvB[8]; ldv8p(hbufB, hvB);

    // hproj of h[t+1]; skip first iteration
    float hpA = bHp + dot16p(wHp, hvA);
    float hpB = bHp + dot16p(wHp, hvB);
    if (low && t != TL - 1){
      hpout[(size_t)(t+1) * NB16]      = hpA;
      hpout[(size_t)(t+1) * NB16 + 16] = hpB;
    }

    float a0A = fmaf(xtA, wx0, b0) + dot16p(w0, hvA);
    float a1A = fmaf(xtA, wx1, b1) + dot16p(w1, hvA);
    float a0B = fmaf(xtB, wx0, b0) + dot16p(w0, hvB);
    float a1B = fmaf(xtB, wx1, b1) + dot16p(w1, hvB);

    float act1A = sigf(a0A);
    float act2A = __fdividef(sc2, 1.f + __expf(-sc2 * a1A)) - (sc2 - 1.f);
    float act1B = sigf(a0B);
    float act2B = __fdividef(sc2, 1.f + __expf(-sc2 * a1B)) - (sc2 - 1.f);

    float pA = low ? act1A * act2A : act1A;   // low: sig(i)*tanh(g); high: sig(f)
    float qA = act2A;                          // high: sig(o)
    float pB = low ? act1B * act2B : act1B;
    float qB = act2B;

    float ppA = __shfl_xor_sync(FULL, pA, 16);
    float qqA = __shfl_xor_sync(FULL, qA, 16);
    float ppB = __shfl_xor_sync(FULL, pB, 16);
    float qqB = __shfl_xor_sync(FULL, qB, 16);
    __syncwarp();                              // hbuf reads done
    if (low){
      cA = fmaf(ppA, cA, pA);
      hbufA[lo] = qqA * tanh_fast(cA);
      cB = fmaf(ppB, cB, pB);
      hbufB[lo] = qqB * tanh_fast(cB);
    }
    __syncwarp();
    xtA = xnA; xtB = xnB;
  }

  // epilogue: hproj[0] from final h
  {
    uint64_t hvA[8]; ldv8p(hbufA, hvA);
    uint64_t hvB[8]; ldv8p(hbufB, hvB);
    float hpA = bHp + dot16p(wHp, hvA);
    float hpB = bHp + dot16p(wHp, hvB);
    if (low){ hpout[0] = hpA; hpout[16] = hpB; }
  }
}

// ============================================================================
// Phase 2: DKF recurrence. TWO batches per warp (independent chains, shared
// weights), smem staging, 4-deep prefetch ring per batch, packed FFMA2.
// ============================================================================
__global__ __launch_bounds__(64)
void dkf_rec_kernel(const float* __restrict__ eps,
                    const float* __restrict__ cW1,
                    const float* __restrict__ cW2, const float* __restrict__ cb2,
                    const float* __restrict__ eW1, const float* __restrict__ eb1,
                    const float* __restrict__ eW2, const float* __restrict__ eb2,
                    float* __restrict__ out)
{
  const int l = threadIdx.x & 31;
  const int w = threadIdx.x >> 5;
  const int bA = blockIdx.x * 4 + w * 2;
  const int lo = l & 15;

  __shared__ __align__(16) float sm[2][96];
  float* SAA = &sm[w][0];    // a1 A
  float* SAB = &sm[w][16];   // a1 B
  float* SCA = &sm[w][32];   // e1 A
  float* SCB = &sm[w][48];   // e1 B
  float* SZA = &sm[w][64];   // z  A
  float* SZB = &sm[w][80];   // z  B

  // layer A, z-columns of comb_W1, row lo (duplicated across halves)
  uint64_t wAz[8];
  #pragma unroll
  for (int j = 0; j < 8; j++)
    wAz[j] = pk2(cW1[lo*32 + 16 + 2*j], cW1[lo*32 + 16 + 2*j + 1]);

  // fused M row lo: M = eW1 @ cW2 ; bM = eW1 @ cb2 + eb1
  uint64_t wM[8];
  float bM = eb1[lo];
  {
    float e1w[8];
    #pragma unroll
    for (int k = 0; k < 8; k++) e1w[k] = eW1[lo*8 + k];
    #pragma unroll
    for (int cc = 0; cc < 8; cc++){
      float accx = 0.f, accy = 0.f;
      #pragma unroll
      for (int k = 0; k < 8; k++){
        accx = fmaf(e1w[k], cW2[k*16 + 2*cc],     accx);
        accy = fmaf(e1w[k], cW2[k*16 + 2*cc + 1], accy);
      }
      wM[cc] = pk2(accx, accy);
    }
    #pragma unroll
    for (int k = 0; k < 8; k++) bM = fmaf(e1w[k], cb2[k], bM);
  }

  // enc2 (32x16): lane l owns row l
  uint64_t wD[8];
  #pragma unroll
  for (int j = 0; j < 8; j++)
    wD[j] = pk2(eW2[l*16 + 2*j], eW2[l*16 + 2*j + 1]);
  const float bD = eb2[l];

  if (l < 16){ SZA[lo] = 0.f; SZB[lo] = 0.f; }   // z0
  __syncwarp();

  const float* hpp = g_hproj + (size_t)bA * 16 + lo;   // B at +16
  const float* epp = eps     + (size_t)bA * 16 + lo;   // B at +16
  float*       zsp = g_zseq  + (size_t)bA * 16 + lo;   // B at +16
  float*       outp = out    + (size_t)bA * 66;        // B at +66

  // ---- 4-deep prefetch ring, per batch ----
  float hpA0 = __ldg(hpp);
  float hpA1 = __ldg(hpp + (size_t)1 * NB16);
  float hpA2 = __ldg(hpp + (size_t)2 * NB16);
  float hpA3 = __ldg(hpp + (size_t)3 * NB16);
  float hpB0 = __ldg(hpp + 16);
  float hpB1 = __ldg(hpp + (size_t)1 * NB16 + 16);
  float hpB2 = __ldg(hpp + (size_t)2 * NB16 + 16);
  float hpB3 = __ldg(hpp + (size_t)3 * NB16 + 16);
  float epA0 = __ldg(epp);
  float epA1 = __ldg(epp + (size_t)1 * NB16);
  float epA2 = __ldg(epp + (size_t)2 * NB16);
  float epA3 = __ldg(epp + (size_t)3 * NB16);
  float epB0 = __ldg(epp + 16);
  float epB1 = __ldg(epp + (size_t)1 * NB16 + 16);
  float epB2 = __ldg(epp + (size_t)2 * NB16 + 16);
  float epB3 = __ldg(epp + (size_t)3 * NB16 + 16);

  #define DKF_STEP(T, HPA, EPA, HPB, EPB)                                 \
  {                                                                       \
    uint64_t zvA[8]; ldv8p(SZA, zvA);                                     \
    uint64_t zvB[8]; ldv8p(SZB, zvB);                                     \
    float a1A = tanh_fast((HPA) + dot16p(wAz, zvA));                      \
    float a1B = tanh_fast((HPB) + dot16p(wAz, zvB));                      \
    if (l < 16){ SAA[lo] = a1A; SAB[lo] = a1B; }                          \
    __syncwarp();                                                         \
    uint64_t avA[8]; ldv8p(SAA, avA);                                     \
    uint64_t avB[8]; ldv8p(SAB, avB);                                     \
    float e1A = tanh_fast(bM + dot16p(wM, avA));                          \
    float e1B = tanh_fast(bM + dot16p(wM, avB));                          \
    if (l < 16){ SCA[lo] = e1A; SCB[lo] = e1B; }                          \
    __syncwarp();                                                         \
    uint64_t evA[8]; ldv8p(SCA, evA);                                     \
    uint64_t evB[8]; ldv8p(SCB, evB);                                     \
    float e2A = bD + dot16p(wD, evA);                                     \
    float e2B = bD + dot16p(wD, evB);                                     \
    outp[2 + l]      = e2A;                                               \
    outp[66 + 2 + l] = e2B;                                               \
    float lvA = __shfl_xor_sync(FULL, e2A, 16);                           \
    float lvB = __shfl_xor_sync(FULL, e2B, 16);                           \
    float znA = fmaf((EPA), __expf(0.5f * lvA), e2A);                     \
    float znB = fmaf((EPB), __expf(0.5f * lvB), e2B);                     \
    if (l < 16){                                                          \
      SZA[lo] = znA; SZB[lo] = znB;                                       \
      zsp[(size_t)(T) * NB16]      = znA;                                 \
      zsp[(size_t)(T) * NB16 + 16] = znB;                                 \
    }                                                                     \
    __syncwarp();                                                         \
    outp += (size_t)NB * 66;                                              \
  }

  #pragma unroll 1
  for (int t = 0; t < TL; t += 4){
    int t4 = t + 4; if (t4 > TL-1) t4 = TL-1;
    int t5 = t + 5; if (t5 > TL-1) t5 = TL-1;
    int t6 = t + 6; if (t6 > TL-1) t6 = TL-1;
    int t7 = t + 7; if (t7 > TL-1) t7 = TL-1;

    float hpa = __ldg(hpp + (size_t)t4 * NB16);
    float hpb = __ldg(hpp + (size_t)t4 * NB16 + 16);
    float epa = __ldg(epp + (size_t)t4 * NB16);
    float epb = __ldg(epp + (size_t)t4 * NB16 + 16);
    DKF_STEP(t + 0, hpA0, epA0, hpB0, epB0);
    hpA0 = hpa; hpB0 = hpb; epA0 = epa; epB0 = epb;

    hpa = __ldg(hpp + (size_t)t5 * NB16);
    hpb = __ldg(hpp + (size_t)t5 * NB16 + 16);
    epa = __ldg(epp + (size_t)t5 * NB16);
    epb = __ldg(epp + (size_t)t5 * NB16 + 16);
    DKF_STEP(t + 1, hpA1, epA1, hpB1, epB1);
    hpA1 = hpa; hpB1 = hpb; epA1 = epa; epB1 = epb;

    hpa = __ldg(hpp + (size_t)t6 * NB16);
    hpb = __ldg(hpp + (size_t)t6 * NB16 + 16);
    epa = __ldg(epp + (size_t)t6 * NB16);
    epb = __ldg(epp + (size_t)t6 * NB16 + 16);
    DKF_STEP(t + 2, hpA2, epA2, hpB2, epB2);
    hpA2 = hpa; hpB2 = hpb; epA2 = epa; epB2 = epb;

    hpa = __ldg(hpp + (size_t)t7 * NB16);
    hpb = __ldg(hpp + (size_t)t7 * NB16 + 16);
    epa = __ldg(epp + (size_t)t7 * NB16);
    epb = __ldg(epp + (size_t)t7 * NB16 + 16);
    DKF_STEP(t + 3, hpA3, epA3, hpB3, epB3);
    hpA3 = hpa; hpB3 = hpb; epA3 = epa; epB3 = epb;
  }
  #undef DKF_STEP
}

// ============================================================================
// Phase 3: decoder + transition. Fully parallel over all (t,b) positions.
// ============================================================================
#define OD_W1 0
#define OD_B1 256
#define OD_W2 272
#define OD_B2 304
#define OT_W1 308
#define OT_B1 564
#define OT_W2 580
#define OT_B2 1092
#define SW_TOT 1124

__device__ __forceinline__ float sdot16(const float* srow, const float v[16]){
  float a0 = 0.f, a1 = 0.f, a2 = 0.f, a3 = 0.f;
  #pragma unroll
  for (int j = 0; j < 4; j++){
    float4 q = reinterpret_cast<const float4*>(srow)[j];
    a0 = fmaf(q.x, v[4*j+0], a0);
    a1 = fmaf(q.y, v[4*j+1], a1);
    a2 = fmaf(q.z, v[4*j+2], a2);
    a3 = fmaf(q.w, v[4*j+3], a3);
  }
  return (a0 + a1) + (a2 + a3);
}

__global__ __launch_bounds__(256)
void dectr_kernel(const float* __restrict__ dW1, const float* __restrict__ db1,
                  const float* __restrict__ dW2, const float* __restrict__ db2,
                  const float* __restrict__ tW1, const float* __restrict__ tb1,
                  const float* __restrict__ tW2, const float* __restrict__ tb2,
                  float* __restrict__ out)
{
  __shared__ __align__(16) float s[SW_TOT];
  const int tid = threadIdx.x;
  for (int i = tid; i < 256; i += 256) s[OD_W1 + i] = dW1[i];
  if (tid < 16)  s[OD_B1 + tid] = db1[tid];
  if (tid < 32)  s[OD_W2 + tid] = dW2[tid];
  if (tid < 2)   s[OD_B2 + tid] = db2[tid];
  for (int i = tid; i < 256; i += 256) s[OT_W1 + i] = tW1[i];
  if (tid < 16)  s[OT_B1 + tid] = tb1[tid];
  for (int i = tid; i < 512; i += 256) s[OT_W2 + i] = tW2[i];
  if (tid < 32)  s[OT_B2 + tid] = tb2[tid];
  __syncthreads();

  const size_t pos = (size_t)blockIdx.x * 256 + tid;   // t*NB + b
  const float* zp_ptr = g_zseq + pos * 16;

  float z[16]; ldv16(zp_ptr, z);
  float zp[16];
  if (pos >= NB){ ldv16(zp_ptr - (size_t)NB * 16, zp); }
  else {
    #pragma unroll
    for (int j = 0; j < 16; j++) zp[j] = 0.f;
  }

  float* ob = out + pos * 66;

  float d1[16];
  #pragma unroll
  for (int r = 0; r < 16; r++)
    d1[r] = tanh_fast(s[OD_B1 + r] + sdot16(&s[OD_W1 + r*16], z));
  float2 dx;
  dx.x = s[OD_B2 + 0] + sdot16(&s[OD_W2 + 0],  d1);
  dx.y = s[OD_B2 + 1] + sdot16(&s[OD_W2 + 16], d1);
  *reinterpret_cast<float2*>(ob) = dx;    // mu_x, logvar_x

  float t1[16];
  #pragma unroll
  for (int r = 0; r < 16; r++)
    t1[r] = tanh_fast(s[OT_B1 + r] + sdot16(&s[OT_W1 + r*16], zp));
  #pragma unroll
  for (int r = 0; r < 32; r += 2){
    float2 tv;
    tv.x = s[OT_B2 + r]     + sdot16(&s[OT_W2 + r*16],     t1);
    tv.y = s[OT_B2 + r + 1] + sdot16(&s[OT_W2 + (r+1)*16], t1);
    *reinterpret_cast<float2*>(ob + 34 + r) = tv;   // mu_tr / logvar_tr
  }
}

extern "C" void kernel_launch(void* const* d_in, const int* in_sizes, int n_in,
                              void* d_out, int out_size)
{
  const float* x   = (const float*)d_in[0];
  const float* eps = (const float*)d_in[1];
  const float* Wih = (const float*)d_in[2];
  const float* Whh = (const float*)d_in[3];
  const float* bih = (const float*)d_in[4];
  const float* bhh = (const float*)d_in[5];
  const float* cW1 = (const float*)d_in[6];
  const float* cb1 = (const float*)d_in[7];
  const float* cW2 = (const float*)d_in[8];
  const float* cb2 = (const float*)d_in[9];
  const float* eW1 = (const float*)d_in[10];
  const float* eb1 = (const float*)d_in[11];
  const float* eW2 = (const float*)d_in[12];
  const float* eb2 = (const float*)d_in[13];
  const float* dW1 = (const float*)d_in[14];
  const float* db1 = (const float*)d_in[15];
  const float* dW2 = (const float*)d_in[16];
  const float* db2 = (const float*)d_in[17];
  const float* tW1 = (const float*)d_in[18];
  const float* tb1 = (const float*)d_in[19];
  const float* tW2 = (const float*)d_in[20];
  const float* tb2 = (const float*)d_in[21];
  float* out = (float*)d_out;

  lstm_bwd_kernel<<<NB/4, 64>>>(x, Wih, Whh, bih, bhh, cW1, cb1);
  dkf_rec_kernel<<<NB/4, 64>>>(eps, cW1, cW2, cb2, eW1, eb1, eW2, eb2, out);
  dectr_kernel<<<(TL*NB)/256, 256>>>(dW1, db1, dW2, db2, tW1, tb1, tW2, tb2, out);
}